// round 9
// baseline (speedup 1.0000x reference)
#include <cuda_runtime.h>
#include <cuda_bf16.h>
#include <cstddef>
#include <cstdint>

// Problem constants (CTCLoss_56298431315981): T=1024, B=32, C=1024, L=128
constexpr int kT = 1024;
constexpr int kB = 32;
constexpr int kC = 1024;
constexpr int kL = 128;
constexpr int kRowF = 132;       // row: plab[0..127], blank@128, lgmax@129, pad
constexpr int kTP = kT + 8;      // pad: prefetch row t+6 <= 1029 always valid

// Scratch (static __device__ — no allocations allowed)
__device__ float g_E[(size_t)kB * kTP * kRowF];
__device__ float g_nll[kB];

constexpr int NEGI = -(1 << 28);
constexpr int kDel = 10;         // frame-gap cap (bits/lane). With rescale every
                                 // 3 steps: in-warp local bound ~2^35, one
                                 // boundary crossing ~2^80, +2 steps ~2^103 <
                                 // 2^127. (R8's Δ=24/6-step hit 2^154 -> inf.)

// 2^d as product of two fp32 powers of two (self-rescale path).
__device__ __forceinline__ void twoFactor(int d, float& f1, float& f2)
{
    d = max(min(d, 252), -300);
    if (d < -252) { f1 = 0.f; f2 = 0.f; return; }
    const int dh = d / 2;
    f1 = __int_as_float((dh + 127) << 23);
    f2 = __int_as_float((d - dh + 127) << 23);
}
// Single-factor 2^d for halo conversion: |d| <= ~80 by the frame-cap analysis;
// d < -126 -> halo provably negligible, flush to 0.
__device__ __forceinline__ float oneFactor(int d)
{
    d = min(d, 127);
    if (d < -126) return 0.f;
    return __int_as_float((d + 127) << 23);
}

// ---------------------------------------------------------------------------
// Kernel 1: per-(t,b) softmax; row-max-normalized probs: 128 label probs +
// blank + log2(rowmax). One warp per row; t-reversed so small-t rows are
// written last (L2-hot for the DP start).
// ---------------------------------------------------------------------------
__global__ void __launch_bounds__(256) ctc_emis_kernel(
    const float* __restrict__ data, const int* __restrict__ labels)
{
    __shared__ float sh[8][kC];
    __shared__ int   shlab[8][kL];
    const int warp = threadIdx.x >> 5;
    const int lane = threadIdx.x & 31;
    const int row  = (kT * kB - 1) - ((blockIdx.x << 3) + warp); // reversed
    const int t = row >> 5;                      // B == 32
    const int b = row & 31;

    reinterpret_cast<int4*>(shlab[warp])[lane] =
        reinterpret_cast<const int4*>(labels + b * kL)[lane];

    const float4* src = reinterpret_cast<const float4*>(data + (size_t)(t * kB + b) * kC);

    float m = -3.4e38f;
    float4 v[8];
#pragma unroll
    for (int i = 0; i < 8; i++) {
        v[i] = src[(i << 5) + lane];
        reinterpret_cast<float4*>(sh[warp])[(i << 5) + lane] = v[i];
        m = fmaxf(m, fmaxf(fmaxf(v[i].x, v[i].y), fmaxf(v[i].z, v[i].w)));
    }
#pragma unroll
    for (int o = 16; o; o >>= 1) m = fmaxf(m, __shfl_xor_sync(0xffffffffu, m, o));

    float ssum = 0.f;
#pragma unroll
    for (int i = 0; i < 8; i++) {
        ssum += __expf(v[i].x - m) + __expf(v[i].y - m) +
                __expf(v[i].z - m) + __expf(v[i].w - m);
    }
#pragma unroll
    for (int o = 16; o; o >>= 1) ssum += __shfl_xor_sync(0xffffffffu, ssum, o);

    const float lse = m + __logf(ssum);

    __syncwarp();  // smem stores (data row + labels) visible warp-wide

    const float blank = __expf(sh[warp][0] - lse);   // class 0 = blank
    float p[4];
#pragma unroll
    for (int j = 0; j < 4; j++)
        p[j] = __expf(sh[warp][shlab[warp][4 * lane + j]] - lse);

    float pmax = fmaxf(fmaxf(fmaxf(p[0], p[1]), fmaxf(p[2], p[3])), blank);
#pragma unroll
    for (int o = 16; o; o >>= 1) pmax = fmaxf(pmax, __shfl_xor_sync(0xffffffffu, pmax, o));

    const float r   = __frcp_rn(pmax);
    const float lg2 = -__log2f(r);

    float* dst = g_E + ((size_t)b * kTP + t) * kRowF;
    reinterpret_cast<float4*>(dst)[lane] =
        make_float4(p[0] * r, p[1] * r, p[2] * r, p[3] * r);
    if (lane == 0) {
        dst[128] = blank * r;
        dst[129] = lg2;
    }
}

// ---------------------------------------------------------------------------
// Kernel 2: CTC forward DP across 4 warps (one per SMSP). Thread dt owns
// states 2dt, 2dt+1 (tid 127 also state 256). Linear domain, per-lane block
// floating point; frame alignment via warp prefix-max scan (cap kDel bits per
// lane), rescale every 3 steps; cross-warp halo through smem, one
// __syncthreads per step.
// ---------------------------------------------------------------------------
__global__ void __launch_bounds__(128) ctc_dp_kernel(
    const int* __restrict__ labels, const int* __restrict__ llen,
    const int* __restrict__ dlen)
{
    __shared__ float2 halo[4][4];   // [slot t&3][consumer warp]
    __shared__ float  A0s[128], A1s[128];
    __shared__ float  A2s;
    __shared__ int    Xs[128];

    const unsigned FULL = 0xffffffffu;
    const int b    = blockIdx.x;
    const int tid  = threadIdx.x;
    const int lane = tid & 31;
    const int w    = tid >> 5;

    const int len = llen[b];
    const int Tb  = dlen[b];                 // 512..1024
    const float* __restrict__ Eb = g_E + (size_t)b * kTP * kRowF;
    const int* __restrict__ lab  = labels + b * kL;

    // skip legality for odd state 2*tid+1 (label tid)
    float allow1 = 0.f;
    if (tid >= 1) allow1 = (lab[tid] != lab[tid - 1]) ? 1.f : 0.f;

    const bool isW = (lane == 31) && (tid != 127);  // halo writer
    const bool isR = (lane == 0) && (w != 0);       // halo reader

    // t=0 init: alpha[0]=blank, alpha[1]=plab[0] (thread 0 only)
    float a0 = (tid == 0) ? __ldg(&Eb[128]) : 0.f;
    float a1 = (tid == 0) ? __ldg(&Eb[0])   : 0.f;
    float a2 = 0.f;                                  // state 256 (tid 127)
    float lgsum = __ldg(&Eb[129]);                   // t=0 row log2(pmax)

    int   X    = 0;                                  // per-lane frame exponent
    float sD   = (lane == 0) ? 0.f : 1.f;            // intra-warp halo factor
    int   X31i = 0;                                  // cached pred-warp lane31 X

    // 6-deep emission prefetch ring: Pl = plab[tid], Pb = (blank, lgmax)
    float  Pl[6];
    float2 Pb[6];
#pragma unroll
    for (int q = 0; q < 6; q++) {
        const float* r = Eb + (size_t)(1 + q) * kRowF;
        Pl[q] = __ldg(r + tid);
        Pb[q] = __ldg(reinterpret_cast<const float2*>(r + 128));
    }

    int t = 1;

    // Per-lane rescale with prefix-max frame cap:
    // Xn_l = max_m<=l (cand_m - kDel*(l-m)); cross-warp seed from cached X31.
    auto rescale = [&]() {
        float m = fmaxf(a0, a1);
        if (tid == 127) m = fmaxf(m, a2);
        const bool nz = (m > 0.f);
        const int  e    = nz ? (((__float_as_int(m) >> 23) & 0xff) - 127) : 0;
        const int  cand = nz ? (X + e) : NEGI;
        int z = cand + kDel * lane;
        if (isR) z = max(z, X31i - kDel);    // seed from pred warp's frame
#pragma unroll
        for (int o = 1; o < 32; o <<= 1) {
            const int v = __shfl_up_sync(FULL, z, o);
            if (lane >= o) z = max(z, v);
        }
        int Xn = z - kDel * lane;
        if (z < NEGI / 2) Xn = X;            // fully empty prefix: keep frame
        float f1, f2;
        twoFactor(X - Xn, f1, f2);
        a0 = (a0 * f1) * f2;
        a1 = (a1 * f1) * f2;
        a2 = (a2 * f1) * f2;
        X = Xn;
        const int Xp = __shfl_up_sync(FULL, X, 1);
        sD = (lane == 0) ? 0.f : oneFactor(Xp - X);  // gap <= kDel by the scan
    };

    // One DP step consuming (pl, pb); refills them with row t+6.
    auto step = [&](float& pl, float2& pb, bool resc) {
        if (resc) rescale();
        if (isW) halo[t & 3][w + 1] = make_float2(a1, __int_as_float(X));
        __syncthreads();
        float h1 = __shfl_up_sync(FULL, a1, 1) * sD;   // alpha[2*tid-1]
        if (isR) {
            const float2 hv = halo[t & 3][w];
            X31i = __float_as_int(hv.y);
            h1 = hv.x * oneFactor(X31i - X);           // bounded gap, see kDel
        }
        const float blankp = pb.x;
        const float na2 = (a2 + a1) * blankp;              // state 256 (tid127)
        const float na0 = (a0 + h1) * blankp;              // even state: no skip
        const float na1 = fmaf(allow1, h1, a1 + a0) * pl;  // odd state
        lgsum += pb.y;
        a0 = na0; a1 = na1; a2 = na2;
        const float* r = Eb + (size_t)(t + 6) * kRowF;
        pl = __ldg(r + tid);
        pb = __ldg(reinterpret_cast<const float2*>(r + 128));
        ++t;
    };

    // Rescale cadence: every 3 steps (group positions 0 and 3).
    for (; t + 5 < Tb; ) {
        step(Pl[0], Pb[0], true);
        step(Pl[1], Pb[1], false);
        step(Pl[2], Pb[2], false);
        step(Pl[3], Pb[3], true);
        step(Pl[4], Pb[4], false);
        step(Pl[5], Pb[5], false);
    }
    // Tail <= 5 steps; Tb uniform per CTA so barriers stay uniform.
    if (t < Tb) step(Pl[0], Pb[0], true);
    if (t < Tb) step(Pl[1], Pb[1], false);
    if (t < Tb) step(Pl[2], Pb[2], false);
    if (t < Tb) step(Pl[3], Pb[3], true);
    if (t < Tb) step(Pl[4], Pb[4], false);

    // Readout: alpha[2*len] (blank) + alpha[2*len-1] (last label)
    A0s[tid] = a0;
    A1s[tid] = a1;
    Xs[tid]  = X;
    if (tid == 127) A2s = a2;
    __syncthreads();
    if (tid == 0) {
        const int sB = 2 * len;
        float aB; int XB;
        if (sB == 256) { aB = A2s; XB = Xs[127]; }
        else           { aB = A0s[sB >> 1]; XB = Xs[sB >> 1]; }
        const float aL = A1s[len - 1];
        const int   XL = Xs[len - 1];
        const float yB = (aB > 0.f) ? (log2f(aB) + (float)XB) : -1e30f;
        const float yL = (aL > 0.f) ? (log2f(aL) + (float)XL) : -1e30f;
        const float mx = fmaxf(yB, yL);
        const float rr = mx + log2f(exp2f(yB - mx) + exp2f(yL - mx)) + lgsum;
        g_nll[b] = -rr * 0.69314718055994530942f;   // log2 -> ln
    }
}

// ---------------------------------------------------------------------------
// Kernel 3: mean over batch -> d_out[0]. Deterministic (no atomics).
// ---------------------------------------------------------------------------
__global__ void ctc_finish_kernel(float* __restrict__ out)
{
    float v = g_nll[threadIdx.x];
#pragma unroll
    for (int o = 16; o; o >>= 1) v += __shfl_xor_sync(0xffffffffu, v, o);
    if (threadIdx.x == 0) out[0] = v * (1.0f / kB);
}

extern "C" void kernel_launch(void* const* d_in, const int* in_sizes, int n_in,
                              void* d_out, int out_size)
{
    const int*   labels       = (const int*)d_in[0];
    const float* data         = (const float*)d_in[1];
    const int*   label_length = (const int*)d_in[2];
    const int*   data_length  = (const int*)d_in[3];
    float*       out          = (float*)d_out;

    ctc_emis_kernel<<<(kT * kB) / 8, 256>>>(data, labels);
    ctc_dp_kernel<<<kB, 128>>>(labels, label_length, data_length);
    ctc_finish_kernel<<<1, 32>>>(out);
}

// round 10
// speedup vs baseline: 1.0789x; 1.0789x over previous
#include <cuda_runtime.h>
#include <cuda_bf16.h>
#include <cstddef>
#include <cstdint>

// Problem constants (CTCLoss_56298431315981): T=1024, B=32, C=1024, L=128
constexpr int kT = 1024;
constexpr int kB = 32;
constexpr int kC = 1024;
constexpr int kL = 128;
constexpr int kS = 2 * kL + 1;   // 257 extended states
constexpr int kRow = 256;        // floats per (b,t) row: 2 comps x 32 lanes x 4
constexpr int kTP = kT + 16;     // pad: prefetch of t+12 always in-bounds

// Scratch (static __device__ — no allocations allowed)
// Row layout (float4 view): comp0[lane] = {p(5l),p(5l+1),p(5l+2),p(5l+3)},
// comp1[lane] = {p(5l+4), blank, log2(rowmax), 0}. p(k) = prob of label k,
// zero-masked for k >= 128. All row-max normalized.
__device__ float g_E[(size_t)kB * kTP * kRow];
__device__ float g_nll[kB];

// ---------------------------------------------------------------------------
// 2^d as a product of two representable fp32 powers of two. |d|<=252 exact;
// d<-252 flushes to 0. Factors must stay separate (product can be inf;
// 0 * f1 * f2 must remain 0 for empty-lane halos).
// ---------------------------------------------------------------------------
__device__ __forceinline__ void twoFactor(int d, float& f1, float& f2)
{
    d = max(min(d, 252), -300);
    if (d < -252) { f1 = 0.f; f2 = 0.f; return; }
    const int dh = d / 2;  // trunc toward 0: both halves stay in [-126,126]
    f1 = __int_as_float((dh + 127) << 23);
    f2 = __int_as_float((d - dh + 127) << 23);
}

// ---------------------------------------------------------------------------
// Kernel 1: per-(t,b) softmax; row-max-normalized probs in DP-native layout.
// One warp per row; t-reversed so small-t rows are written last (L2-hot for
// the DP start).
// ---------------------------------------------------------------------------
__global__ void __launch_bounds__(256) ctc_emis_kernel(
    const float* __restrict__ data, const int* __restrict__ labels)
{
    __shared__ float sh[8][kC];
    __shared__ int   shlab[8][kL];
    const int warp = threadIdx.x >> 5;
    const int lane = threadIdx.x & 31;
    const int row  = (kT * kB - 1) - ((blockIdx.x << 3) + warp); // reversed
    const int t = row >> 5;                      // B == 32
    const int b = row & 31;

    reinterpret_cast<int4*>(shlab[warp])[lane] =
        reinterpret_cast<const int4*>(labels + b * kL)[lane];

    const float4* src = reinterpret_cast<const float4*>(data + (size_t)(t * kB + b) * kC);

    float m = -3.4e38f;
    float4 v[8];
#pragma unroll
    for (int i = 0; i < 8; i++) {
        v[i] = src[(i << 5) + lane];
        reinterpret_cast<float4*>(sh[warp])[(i << 5) + lane] = v[i];
        m = fmaxf(m, fmaxf(fmaxf(v[i].x, v[i].y), fmaxf(v[i].z, v[i].w)));
    }
#pragma unroll
    for (int o = 16; o; o >>= 1) m = fmaxf(m, __shfl_xor_sync(0xffffffffu, m, o));

    float ssum = 0.f;
#pragma unroll
    for (int i = 0; i < 8; i++) {
        ssum += __expf(v[i].x - m) + __expf(v[i].y - m) +
                __expf(v[i].z - m) + __expf(v[i].w - m);
    }
#pragma unroll
    for (int o = 16; o; o >>= 1) ssum += __shfl_xor_sync(0xffffffffu, ssum, o);

    const float lse = m + __logf(ssum);

    __syncwarp();  // smem stores (data row + labels) visible warp-wide

    const float blank = __expf(sh[warp][0] - lse);   // class 0 = blank
    float p[5];
#pragma unroll
    for (int j = 0; j < 5; j++) {
        const int idx = 5 * lane + j;
        p[j] = (idx < kL) ? __expf(sh[warp][shlab[warp][idx]] - lse) : 0.f;
    }

    float pmax = fmaxf(fmaxf(fmaxf(p[0], p[1]), fmaxf(p[2], p[3])),
                       fmaxf(p[4], blank));
#pragma unroll
    for (int o = 16; o; o >>= 1) pmax = fmaxf(pmax, __shfl_xor_sync(0xffffffffu, pmax, o));

    const float r   = __frcp_rn(pmax);
    const float lg2 = -__log2f(r);

    float4* dst = reinterpret_cast<float4*>(g_E + ((size_t)b * kTP + t) * kRow);
    dst[lane]      = make_float4(p[0] * r, p[1] * r, p[2] * r, p[3] * r);
    dst[32 + lane] = make_float4(p[4] * r, blank * r, lg2, 0.f);
}

// ---------------------------------------------------------------------------
// Kernel 2: CTC forward DP, linear domain, per-lane block floating point with
// 2-lane frame-gap cap, rescale every 6 steps. One warp per batch element;
// lane l owns states [10l, 10l+10) = 5 (even,odd) pairs. Pair alignment means
// only ONE halo value (alpha[10l-1]) crosses lanes. Even states use the shared
// blank emission and have no skip transition. No barriers, no MUFU, no local
// memory.
// ---------------------------------------------------------------------------
__global__ void __launch_bounds__(32) ctc_dp_kernel(
    const int* __restrict__ labels, const int* __restrict__ llen,
    const int* __restrict__ dlen)
{
    const unsigned FULL = 0xffffffffu;
    const int NEGI = -(1 << 28);
    const int b    = blockIdx.x;
    const int lane = threadIdx.x;

    const int len = llen[b];
    const int Tb  = dlen[b];               // 512..1024
    const float* __restrict__ Eb = g_E + (size_t)b * kTP * kRow;
    const int* __restrict__ lab  = labels + b * kL;

    // skip legality for odd states 10l+2k+1 (label 5l+k)
    float allow[5];
#pragma unroll
    for (int k = 0; k < 5; k++) {
        const int li = 5 * lane + k;       // label index
        bool al = false;
        if (li >= 1 && li < kL) al = (lab[li] != lab[li - 1]);
        allow[k] = al ? 1.0f : 0.0f;
    }

    float a[10];
#pragma unroll
    for (int j = 0; j < 10; j++) a[j] = 0.f;
    if (lane == 0) {
        a[0] = __ldg(&Eb[129]);  // t=0 state 0: blank (comp1 lane0 .y)
        a[1] = __ldg(&Eb[0]);    // t=0 state 1: label 0 (comp0 lane0 .x)
    }
    float lgsum = __ldg(&Eb[130]);         // t=0 row log2(pmax)
    int   X   = 0;
    float sD1 = (lane == 0) ? 0.f : 1.f;   // halo frame factor = sD1*sD2 (split!)
    float sD2 = (lane == 0) ? 0.f : 1.f;

    // 12-deep emission prefetch ring (rows t=1..12; Tb >= 512 so all valid)
    float4 P[12][2];
#pragma unroll
    for (int q = 0; q < 12; q++) {
        const float4* r = reinterpret_cast<const float4*>(Eb + (size_t)(1 + q) * kRow);
        P[q][0] = __ldg(r + lane);
        P[q][1] = __ldg(r + 32 + lane);
    }

    auto dostep = [&](const float4* Pq) {
        float h1 = __shfl_up_sync(FULL, a[9], 1);   // alpha[10l-1] (pred frame)
        h1 = (h1 * sD1) * sD2;                      // convert to local frame
        const float bl = Pq[1].y;                   // blank prob
        lgsum += Pq[1].z;                           // row log2(pmax)
        float na[10];
        na[0] = (a[0] + h1) * bl;
        na[1] = fmaf(allow[0], h1,   a[1] + a[0]) * Pq[0].x;
        na[2] = (a[2] + a[1]) * bl;
        na[3] = fmaf(allow[1], a[1], a[3] + a[2]) * Pq[0].y;
        na[4] = (a[4] + a[3]) * bl;
        na[5] = fmaf(allow[2], a[3], a[5] + a[4]) * Pq[0].z;
        na[6] = (a[6] + a[5]) * bl;
        na[7] = fmaf(allow[3], a[5], a[7] + a[6]) * Pq[0].w;
        na[8] = (a[8] + a[7]) * bl;
        na[9] = fmaf(allow[4], a[7], a[9] + a[8]) * Pq[1].x;
#pragma unroll
        for (int j = 0; j < 10; j++) a[j] = na[j];
    };

    auto prefetch = [&](float4* Pq, int trow) {
        const float4* r = reinterpret_cast<const float4*>(Eb + (size_t)trow * kRow);
        Pq[0] = __ldg(r + lane);
        Pq[1] = __ldg(r + 32 + lane);
    };

    // Rescale with 2-lane frame cap (alignment propagates 2 lanes/rescale;
    // wavefront moves 12 states = 1.2 lanes per 6-step period).
    auto rescale = [&]() {
        float m = a[0];
#pragma unroll
        for (int j = 1; j < 10; j++) m = fmaxf(m, a[j]);
        const bool nz = (m > 0.f);
        const int  e    = nz ? (((__float_as_int(m) >> 23) & 0xff) - 127) : 0;
        const int  cand = nz ? (X + e) : NEGI;
        const int  c1 = __shfl_up_sync(FULL, cand, 1);
        const int  c2 = __shfl_up_sync(FULL, cand, 2);
        int Xn;
        if (lane == 0) {
            Xn = nz ? cand : X;
        } else {
            const int low  = max(c1 - 24, c2 - 48);
            const int ownc = nz ? cand : NEGI;
            Xn = max(ownc, low);
            if (Xn <= NEGI) Xn = X;                // fully empty region: keep
        }
        float f1, f2;
        twoFactor(X - Xn, f1, f2);                 // rescale own values (split-safe)
#pragma unroll
        for (int j = 0; j < 10; j++) a[j] = (a[j] * f1) * f2;
        X = Xn;
        const int Xp = __shfl_up_sync(FULL, X, 1); // predecessor FINAL frame
        twoFactor(Xp - X, sD1, sD2);
        if (lane == 0) { sD1 = 0.f; sD2 = 0.f; }
    };

    // Main loop: invariant at head P[i] = emissions(row t+i), i=0..11.
    int t = 1;
    for (; t + 11 < Tb; t += 12) {
        dostep(P[0]);  prefetch(P[0],  t + 12);
        dostep(P[1]);  prefetch(P[1],  t + 13);
        dostep(P[2]);  prefetch(P[2],  t + 14);
        dostep(P[3]);  prefetch(P[3],  t + 15);
        dostep(P[4]);  prefetch(P[4],  t + 16);
        dostep(P[5]);  prefetch(P[5],  t + 17);
        rescale();
        dostep(P[6]);  prefetch(P[6],  t + 18);
        dostep(P[7]);  prefetch(P[7],  t + 19);
        dostep(P[8]);  prefetch(P[8],  t + 20);
        dostep(P[9]);  prefetch(P[9],  t + 21);
        dostep(P[10]); prefetch(P[10], t + 22);
        dostep(P[11]); prefetch(P[11], t + 23);
        rescale();
    }
    // Tail (<=11 steps): STATIC indices only (dynamic indexing of P would
    // demote the whole ring to local memory).
    if (t < Tb) { dostep(P[0]); ++t; }
    if (t < Tb) { dostep(P[1]); ++t; }
    if (t < Tb) { dostep(P[2]); ++t; }
    if (t < Tb) { dostep(P[3]); ++t; }
    rescale();
    if (t < Tb) { dostep(P[4]); ++t; }
    if (t < Tb) { dostep(P[5]); ++t; }
    if (t < Tb) { dostep(P[6]); ++t; }
    if (t < Tb) { dostep(P[7]); ++t; }
    rescale();
    if (t < Tb) { dostep(P[8]); ++t; }
    if (t < Tb) { dostep(P[9]); ++t; }
    if (t < Tb) { dostep(P[10]); ++t; }

    // Final: combine alpha[2*len] and alpha[2*len-1]; add back row log2 sums.
    __shared__ float Af[320];
    __shared__ int   Xf[32];
#pragma unroll
    for (int j = 0; j < 10; j++) Af[10 * lane + j] = a[j];
    Xf[lane] = X;
    __syncwarp();
    if (lane == 0) {
        const int sB = 2 * len, sL = sB - 1;
        const float aB = Af[sB], aL = Af[sL];
        const float yB = (aB > 0.f) ? (log2f(aB) + (float)Xf[sB / 10]) : -1e30f;
        const float yL = (aL > 0.f) ? (log2f(aL) + (float)Xf[sL / 10]) : -1e30f;
        const float mx = fmaxf(yB, yL);
        const float rr = mx + log2f(exp2f(yB - mx) + exp2f(yL - mx)) + lgsum;
        g_nll[b] = -rr * 0.69314718055994530942f;   // log2 -> ln
    }
}

// ---------------------------------------------------------------------------
// Kernel 3: mean over batch -> d_out[0]. Deterministic (no atomics).
// ---------------------------------------------------------------------------
__global__ void ctc_finish_kernel(float* __restrict__ out)
{
    float v = g_nll[threadIdx.x];
#pragma unroll
    for (int o = 16; o; o >>= 1) v += __shfl_xor_sync(0xffffffffu, v, o);
    if (threadIdx.x == 0) out[0] = v * (1.0f / kB);
}

extern "C" void kernel_launch(void* const* d_in, const int* in_sizes, int n_in,
                              void* d_out, int out_size)
{
    const int*   labels       = (const int*)d_in[0];
    const float* data         = (const float*)d_in[1];
    const int*   label_length = (const int*)d_in[2];
    const int*   data_length  = (const int*)d_in[3];
    float*       out          = (float*)d_out;

    ctc_emis_kernel<<<(kT * kB) / 8, 256>>>(data, labels);
    ctc_dp_kernel<<<kB, 32>>>(labels, label_length, data_length);
    ctc_finish_kernel<<<1, 32>>>(out);
}

// round 11
// speedup vs baseline: 2.1708x; 2.0119x over previous
#include <cuda_runtime.h>
#include <cuda_bf16.h>
#include <cstddef>
#include <cstdint>

// Problem constants (CTCLoss_56298431315981): T=1024, B=32, C=1024, L=128
constexpr int kT = 1024;
constexpr int kB = 32;
constexpr int kC = 1024;
constexpr int kL = 128;
constexpr int kS = 2 * kL + 1;   // 257 extended states
constexpr int kRow = 256;        // floats per (b,t) row: 2 comps x 32 lanes x 4
constexpr int kTP = kT + 16;     // pad: forward prefetch t+23 in-bounds

// Scratch (static __device__ — no allocations allowed)
// Row layout (float4 view): comp0[lane] = {p(5l),p(5l+1),p(5l+2),p(5l+3)},
// comp1[lane] = {p(5l+4), blank, log2(rowmax), 0}; row-max normalized,
// p(k)=0 for k>=128.
__device__ float g_E[(size_t)kB * kTP * kRow];
__device__ float g_nll[kB];

// ---------------------------------------------------------------------------
// 2^d as a product of two representable fp32 powers of two. Split factors are
// load-bearing: product can be inf, and 0*f1*f2 must stay 0 for empty halos.
// ---------------------------------------------------------------------------
__device__ __forceinline__ void twoFactor(int d, float& f1, float& f2)
{
    d = max(min(d, 252), -300);
    if (d < -252) { f1 = 0.f; f2 = 0.f; return; }
    const int dh = d / 2;
    f1 = __int_as_float((dh + 127) << 23);
    f2 = __int_as_float((d - dh + 127) << 23);
}

// ---------------------------------------------------------------------------
// Kernel 1: per-(t,b) softmax; row-max-normalized probs in DP-native layout.
// MIDDLE-OUT t order: rows near t=0 and t=T-1 are written LAST, so both DP
// warps (forward from 0, backward from Tb-1) start on L2-hot rows.
// ---------------------------------------------------------------------------
__global__ void __launch_bounds__(256) ctc_emis_kernel(
    const float* __restrict__ data, const int* __restrict__ labels)
{
    __shared__ float sh[8][kC];
    __shared__ int   shlab[8][kL];
    const int warp = threadIdx.x >> 5;
    const int lane = threadIdx.x & 31;
    const int g    = (blockIdx.x << 3) + warp;   // 0 .. T*B-1
    const int b    = g & 31;
    const int tlin = g >> 5;
    const int jj   = tlin >> 1;
    const int t    = (tlin & 1) ? (512 + jj) : (511 - jj);   // middle-out

    reinterpret_cast<int4*>(shlab[warp])[lane] =
        reinterpret_cast<const int4*>(labels + b * kL)[lane];

    const float4* src = reinterpret_cast<const float4*>(data + (size_t)(t * kB + b) * kC);

    float m = -3.4e38f;
    float4 v[8];
#pragma unroll
    for (int i = 0; i < 8; i++) {
        v[i] = src[(i << 5) + lane];
        reinterpret_cast<float4*>(sh[warp])[(i << 5) + lane] = v[i];
        m = fmaxf(m, fmaxf(fmaxf(v[i].x, v[i].y), fmaxf(v[i].z, v[i].w)));
    }
#pragma unroll
    for (int o = 16; o; o >>= 1) m = fmaxf(m, __shfl_xor_sync(0xffffffffu, m, o));

    float ssum = 0.f;
#pragma unroll
    for (int i = 0; i < 8; i++) {
        ssum += __expf(v[i].x - m) + __expf(v[i].y - m) +
                __expf(v[i].z - m) + __expf(v[i].w - m);
    }
#pragma unroll
    for (int o = 16; o; o >>= 1) ssum += __shfl_xor_sync(0xffffffffu, ssum, o);

    const float lse = m + __logf(ssum);

    __syncwarp();

    const float blank = __expf(sh[warp][0] - lse);
    float p[5];
#pragma unroll
    for (int j = 0; j < 5; j++) {
        const int idx = 5 * lane + j;
        p[j] = (idx < kL) ? __expf(sh[warp][shlab[warp][idx]] - lse) : 0.f;
    }

    float pmax = fmaxf(fmaxf(fmaxf(p[0], p[1]), fmaxf(p[2], p[3])),
                       fmaxf(p[4], blank));
#pragma unroll
    for (int o = 16; o; o >>= 1) pmax = fmaxf(pmax, __shfl_xor_sync(0xffffffffu, pmax, o));

    const float r   = __frcp_rn(pmax);
    const float lg2 = -__log2f(r);

    float4* dst = reinterpret_cast<float4*>(g_E + ((size_t)b * kTP + t) * kRow);
    dst[lane]      = make_float4(p[0] * r, p[1] * r, p[2] * r, p[3] * r);
    dst[32 + lane] = make_float4(p[4] * r, blank * r, lg2, 0.f);
}

// ---------------------------------------------------------------------------
// Kernel 2: CTC forward+backward meet-in-the-middle. One CTA / batch element,
// 2 warps: warp 0 runs alpha for t=0..m, warp 1 runs beta for t=Tb-1..m
// (m = (Tb-1)/2). Each warp: pair-aligned states (lane l owns 10l..10l+9),
// linear domain, per-lane block floating point with 2-lane frame cap, rescale
// every 6 steps, 12-deep LDG ring. L = sum_s alpha_m(s)*beta_m(s).
// ---------------------------------------------------------------------------
__global__ void __launch_bounds__(64) ctc_dp_kernel(
    const int* __restrict__ labels, const int* __restrict__ llen,
    const int* __restrict__ dlen)
{
    __shared__ float AFs[320], BBs[320];
    __shared__ int   XFs[32],  XBs[32];
    __shared__ float LGs[2];

    const unsigned FULL = 0xffffffffu;
    const int NEGI = -(1 << 28);
    const int b    = blockIdx.x;
    const int lane = threadIdx.x & 31;
    const int w    = threadIdx.x >> 5;

    const int len = llen[b];
    const int Tb  = dlen[b];               // 512..1024
    const int mid = (Tb - 1) >> 1;         // meeting time (>=255)
    const float* __restrict__ Eb = g_E + (size_t)b * kTP * kRow;
    const int* __restrict__ lab  = labels + b * kL;

    if (w == 0) {
        // ===================== FORWARD (alpha), t = 0..mid ==================
        float allow[5];
#pragma unroll
        for (int k = 0; k < 5; k++) {
            const int li = 5 * lane + k;
            bool al = false;
            if (li >= 1 && li < kL) al = (lab[li] != lab[li - 1]);
            allow[k] = al ? 1.0f : 0.0f;
        }

        float a[10];
#pragma unroll
        for (int j = 0; j < 10; j++) a[j] = 0.f;
        if (lane == 0) {
            a[0] = __ldg(&Eb[129]);  // t=0 state 0: blank
            a[1] = __ldg(&Eb[0]);    // t=0 state 1: label 0
        }
        float lgsum = __ldg(&Eb[130]);
        int   X   = 0;
        float sD1 = (lane == 0) ? 0.f : 1.f;
        float sD2 = (lane == 0) ? 0.f : 1.f;

        float4 P[12][2];
#pragma unroll
        for (int q = 0; q < 12; q++) {
            const float4* r = reinterpret_cast<const float4*>(Eb + (size_t)(1 + q) * kRow);
            P[q][0] = __ldg(r + lane);
            P[q][1] = __ldg(r + 32 + lane);
        }

        auto dostep = [&](const float4* Pq) {
            float h1 = __shfl_up_sync(FULL, a[9], 1);
            h1 = (h1 * sD1) * sD2;
            const float bl = Pq[1].y;
            lgsum += Pq[1].z;
            float na[10];
            na[0] = (a[0] + h1) * bl;
            na[1] = fmaf(allow[0], h1,   a[1] + a[0]) * Pq[0].x;
            na[2] = (a[2] + a[1]) * bl;
            na[3] = fmaf(allow[1], a[1], a[3] + a[2]) * Pq[0].y;
            na[4] = (a[4] + a[3]) * bl;
            na[5] = fmaf(allow[2], a[3], a[5] + a[4]) * Pq[0].z;
            na[6] = (a[6] + a[5]) * bl;
            na[7] = fmaf(allow[3], a[5], a[7] + a[6]) * Pq[0].w;
            na[8] = (a[8] + a[7]) * bl;
            na[9] = fmaf(allow[4], a[7], a[9] + a[8]) * Pq[1].x;
#pragma unroll
            for (int j = 0; j < 10; j++) a[j] = na[j];
        };
        auto pref = [&](float4* Pq, int trow) {
            const float4* r = reinterpret_cast<const float4*>(Eb + (size_t)trow * kRow);
            Pq[0] = __ldg(r + lane);
            Pq[1] = __ldg(r + 32 + lane);
        };
        auto rescale = [&]() {
            float mm = a[0];
#pragma unroll
            for (int j = 1; j < 10; j++) mm = fmaxf(mm, a[j]);
            const bool nz = (mm > 0.f);
            const int  e    = nz ? (((__float_as_int(mm) >> 23) & 0xff) - 127) : 0;
            const int  cand = nz ? (X + e) : NEGI;
            const int  c1 = __shfl_up_sync(FULL, cand, 1);
            const int  c2 = __shfl_up_sync(FULL, cand, 2);
            int Xn;
            if (lane == 0) {
                Xn = nz ? cand : X;
            } else {
                const int low  = max(c1 - 24, c2 - 48);
                const int ownc = nz ? cand : NEGI;
                Xn = max(ownc, low);
                if (Xn <= NEGI) Xn = X;
            }
            float f1, f2;
            twoFactor(X - Xn, f1, f2);
#pragma unroll
            for (int j = 0; j < 10; j++) a[j] = (a[j] * f1) * f2;
            X = Xn;
            const int Xp = __shfl_up_sync(FULL, X, 1);
            twoFactor(Xp - X, sD1, sD2);
            if (lane == 0) { sD1 = 0.f; sD2 = 0.f; }
        };

        int t = 1;
        for (; t + 11 <= mid; t += 12) {
            dostep(P[0]);  pref(P[0],  t + 12);
            dostep(P[1]);  pref(P[1],  t + 13);
            dostep(P[2]);  pref(P[2],  t + 14);
            dostep(P[3]);  pref(P[3],  t + 15);
            dostep(P[4]);  pref(P[4],  t + 16);
            dostep(P[5]);  pref(P[5],  t + 17);
            rescale();
            dostep(P[6]);  pref(P[6],  t + 18);
            dostep(P[7]);  pref(P[7],  t + 19);
            dostep(P[8]);  pref(P[8],  t + 20);
            dostep(P[9]);  pref(P[9],  t + 21);
            dostep(P[10]); pref(P[10], t + 22);
            dostep(P[11]); pref(P[11], t + 23);
            rescale();
        }
        if (t <= mid) { dostep(P[0]); ++t; }
        if (t <= mid) { dostep(P[1]); ++t; }
        if (t <= mid) { dostep(P[2]); ++t; }
        if (t <= mid) { dostep(P[3]); ++t; }
        rescale();
        if (t <= mid) { dostep(P[4]); ++t; }
        if (t <= mid) { dostep(P[5]); ++t; }
        if (t <= mid) { dostep(P[6]); ++t; }
        if (t <= mid) { dostep(P[7]); ++t; }
        rescale();
        if (t <= mid) { dostep(P[8]); ++t; }
        if (t <= mid) { dostep(P[9]); ++t; }
        if (t <= mid) { dostep(P[10]); ++t; }

#pragma unroll
        for (int j = 0; j < 10; j++) AFs[10 * lane + j] = a[j];
        XFs[lane] = X;
        if (lane == 0) LGs[0] = lgsum;
    } else {
        // ===================== BACKWARD (beta), t = Tb-1..mid ===============
        // beta_t(s) = c(s)+c(s+1)+allow(s+2)*c(s+2), c(s)=e_{t+1}(s)*beta_{t+1}(s)
        float allowB[5];
#pragma unroll
        for (int k = 0; k < 5; k++) {
            const int li = 5 * lane + k + 1;   // label of state s+2 (odd chain)
            bool al = false;
            if (li < kL) al = (lab[li] != lab[li - 1]);
            allowB[k] = al ? 1.0f : 0.0f;
        }

        const int sBl = 2 * len, sLl = sBl - 1;
        float bv[10];
#pragma unroll
        for (int j = 0; j < 10; j++) {
            const int s = 10 * lane + j;
            bv[j] = (s == sBl || s == sLl) ? 1.f : 0.f;
        }
        float lgsum = 0.f;
        int   X   = 0;
        float sB1 = (lane == 31) ? 0.f : 1.f;
        float sB2 = (lane == 31) ? 0.f : 1.f;

        // ring: P[i] = row (tc+1-i); tc = current step time
        int tc = Tb - 2;
        float4 P[12][2];
#pragma unroll
        for (int q = 0; q < 12; q++) {
            const float4* r = reinterpret_cast<const float4*>(Eb + (size_t)(Tb - 1 - q) * kRow);
            P[q][0] = __ldg(r + lane);
            P[q][1] = __ldg(r + 32 + lane);
        }

        auto dostepB = [&](const float4* Pq) {
            const float bl = Pq[1].y;
            lgsum += Pq[1].z;
            float c[10];
            c[0] = bv[0] * bl;  c[1] = bv[1] * Pq[0].x;
            c[2] = bv[2] * bl;  c[3] = bv[3] * Pq[0].y;
            c[4] = bv[4] * bl;  c[5] = bv[5] * Pq[0].z;
            c[6] = bv[6] * bl;  c[7] = bv[7] * Pq[0].w;
            c[8] = bv[8] * bl;  c[9] = bv[9] * Pq[1].x;
            float h0 = __shfl_down_sync(FULL, c[0], 1);
            float h1 = __shfl_down_sync(FULL, c[1], 1);
            h0 = (h0 * sB1) * sB2;
            h1 = (h1 * sB1) * sB2;
            float nb[10];
            nb[0] = c[0] + c[1];
            nb[1] = fmaf(allowB[0], c[3], c[1] + c[2]);
            nb[2] = c[2] + c[3];
            nb[3] = fmaf(allowB[1], c[5], c[3] + c[4]);
            nb[4] = c[4] + c[5];
            nb[5] = fmaf(allowB[2], c[7], c[5] + c[6]);
            nb[6] = c[6] + c[7];
            nb[7] = fmaf(allowB[3], c[9], c[7] + c[8]);
            nb[8] = c[8] + c[9];
            nb[9] = fmaf(allowB[4], h1,   c[9] + h0);
#pragma unroll
            for (int j = 0; j < 10; j++) bv[j] = nb[j];
            --tc;
        };
        auto prefB = [&](float4* Pq, int trow) {
            const float4* r = reinterpret_cast<const float4*>(Eb + (size_t)trow * kRow);
            Pq[0] = __ldg(r + lane);
            Pq[1] = __ldg(r + 32 + lane);
        };
        auto rescaleB = [&]() {
            float mm = bv[0];
#pragma unroll
            for (int j = 1; j < 10; j++) mm = fmaxf(mm, bv[j]);
            const bool nz = (mm > 0.f);
            const int  e    = nz ? (((__float_as_int(mm) >> 23) & 0xff) - 127) : 0;
            const int  cand = nz ? (X + e) : NEGI;
            const int  c1 = __shfl_down_sync(FULL, cand, 1);
            const int  c2 = __shfl_down_sync(FULL, cand, 2);
            int Xn;
            if (lane == 31) {
                Xn = nz ? cand : X;
            } else {
                const int low  = max(c1 - 24, c2 - 48);
                const int ownc = nz ? cand : NEGI;
                Xn = max(ownc, low);
                if (Xn <= NEGI) Xn = X;
            }
            float f1, f2;
            twoFactor(X - Xn, f1, f2);
#pragma unroll
            for (int j = 0; j < 10; j++) bv[j] = (bv[j] * f1) * f2;
            X = Xn;
            const int Xp = __shfl_down_sync(FULL, X, 1);
            twoFactor(Xp - X, sB1, sB2);
            if (lane == 31) { sB1 = 0.f; sB2 = 0.f; }
        };

        int rem = Tb - 1 - mid;              // steps to run
        for (; rem >= 12; rem -= 12) {
            dostepB(P[0]);  prefB(P[0],  tc - 10);   // (tc already decremented)
            dostepB(P[1]);  prefB(P[1],  tc - 10);
            dostepB(P[2]);  prefB(P[2],  tc - 10);
            dostepB(P[3]);  prefB(P[3],  tc - 10);
            dostepB(P[4]);  prefB(P[4],  tc - 10);
            dostepB(P[5]);  prefB(P[5],  tc - 10);
            rescaleB();
            dostepB(P[6]);  prefB(P[6],  tc - 10);
            dostepB(P[7]);  prefB(P[7],  tc - 10);
            dostepB(P[8]);  prefB(P[8],  tc - 10);
            dostepB(P[9]);  prefB(P[9],  tc - 10);
            dostepB(P[10]); prefB(P[10], tc - 10);
            dostepB(P[11]); prefB(P[11], tc - 10);
            rescaleB();
        }
        if (rem > 0) { dostepB(P[0]); --rem; }
        if (rem > 0) { dostepB(P[1]); --rem; }
        if (rem > 0) { dostepB(P[2]); --rem; }
        if (rem > 0) { dostepB(P[3]); --rem; }
        rescaleB();
        if (rem > 0) { dostepB(P[4]); --rem; }
        if (rem > 0) { dostepB(P[5]); --rem; }
        if (rem > 0) { dostepB(P[6]); --rem; }
        if (rem > 0) { dostepB(P[7]); --rem; }
        rescaleB();
        if (rem > 0) { dostepB(P[8]); --rem; }
        if (rem > 0) { dostepB(P[9]); --rem; }
        if (rem > 0) { dostepB(P[10]); --rem; }

#pragma unroll
        for (int j = 0; j < 10; j++) BBs[10 * lane + j] = bv[j];
        XBs[lane] = X;
        if (lane == 0) LGs[1] = lgsum;
    }

    __syncthreads();

    // ===== Combine: log2 L = LSE_s [log2 aF + XF + log2 bB + XB] + lgsums ===
    if (w == 0) {
        float ys[9];
        float ymax = -1e30f;
#pragma unroll
        for (int k = 0; k < 9; k++) {
            const int s = lane + 32 * k;
            float y = -1e30f;
            if (s < kS) {
                const float af = AFs[s], bb = BBs[s];
                if (af > 0.f && bb > 0.f)
                    y = log2f(af) + log2f(bb) + (float)(XFs[s / 10] + XBs[s / 10]);
            }
            ys[k] = y;
            ymax = fmaxf(ymax, y);
        }
#pragma unroll
        for (int o = 16; o; o >>= 1) ymax = fmaxf(ymax, __shfl_xor_sync(FULL, ymax, o));
        float ssum = 0.f;
#pragma unroll
        for (int k = 0; k < 9; k++) ssum += exp2f(ys[k] - ymax);
#pragma unroll
        for (int o = 16; o; o >>= 1) ssum += __shfl_xor_sync(FULL, ssum, o);
        if (lane == 0) {
            const float rr = ymax + log2f(ssum) + LGs[0] + LGs[1];
            g_nll[b] = -rr * 0.69314718055994530942f;   // log2 -> ln
        }
    }
}

// ---------------------------------------------------------------------------
// Kernel 3: mean over batch -> d_out[0]. Deterministic (no atomics).
// ---------------------------------------------------------------------------
__global__ void ctc_finish_kernel(float* __restrict__ out)
{
    float v = g_nll[threadIdx.x];
#pragma unroll
    for (int o = 16; o; o >>= 1) v += __shfl_xor_sync(0xffffffffu, v, o);
    if (threadIdx.x == 0) out[0] = v * (1.0f / kB);
}

extern "C" void kernel_launch(void* const* d_in, const int* in_sizes, int n_in,
                              void* d_out, int out_size)
{
    const int*   labels       = (const int*)d_in[0];
    const float* data         = (const float*)d_in[1];
    const int*   label_length = (const int*)d_in[2];
    const int*   data_length  = (const int*)d_in[3];
    float*       out          = (float*)d_out;

    ctc_emis_kernel<<<(kT * kB) / 8, 256>>>(data, labels);
    ctc_dp_kernel<<<kB, 64>>>(labels, label_length, data_length);
    ctc_finish_kernel<<<1, 32>>>(out);
}